// round 5
// baseline (speedup 1.0000x reference)
#include <cuda_runtime.h>
#include <cuda_bf16.h>

#define Hh 100
#define Ww 136
#define HW (Hh*Ww)      // 13600
#define OH 200
#define OW 272
#define OHW (OH*OW)     // 54400
#define NPARAM 169
#define MAXINST 512

typedef unsigned long long u64;

__device__ float g_scratch[MAXINST * 3];   // per-instance (inter, ssum, tsum)

// ---- packed f32x2 helpers ----
__device__ __forceinline__ u64 pack2(float a, float b) {
    u64 r; asm("mov.b64 %0, {%1, %2};" : "=l"(r) : "f"(a), "f"(b)); return r;
}
__device__ __forceinline__ void unpack2(u64 v, float& a, float& b) {
    asm("mov.b64 {%0, %1}, %2;" : "=f"(a), "=f"(b) : "l"(v));
}
__device__ __forceinline__ u64 fma2(u64 a, u64 b, u64 c) {
    u64 d; asm("fma.rn.f32x2 %0, %1, %2, %3;" : "=l"(d) : "l"(a), "l"(b), "l"(c)); return d;
}
__device__ __forceinline__ u64 relu2(u64 v) {
    float a, b; unpack2(v, a, b);
    return pack2(fmaxf(a, 0.f), fmaxf(b, 0.f));
}
__device__ __forceinline__ float sigm(float z) {
    float t; asm("tanh.approx.f32 %0, %1;" : "=f"(t) : "f"(z * 0.5f));
    return fmaf(t, 0.5f, 0.5f);
}

// params layout: w0[8][10]@0, w1[8][8]@80, w2[8]@144, b0[8]@152, b1[8]@160, b2@168

__global__ void dmh_zero() {
    for (int i = threadIdx.x; i < MAXINST * 3; i += blockDim.x)
        g_scratch[i] = 0.0f;
}

// grid = 2 * n_inst; block b handles instance b>>1, row-half b&1.
// half 0: input rows [0,50)  -> output rows [0,100)
// half 1: input rows [49,100) (halo row 49) -> output rows [100,200)
__global__ void __launch_bounds__(128, 4)
dmh_kernel(const float* __restrict__ mask_feats,
           const float* __restrict__ params,
           const float* __restrict__ locs,
           const float* __restrict__ gt,
           const int*   __restrict__ im_inds,
           const int*   __restrict__ fpn_levels)
{
    extern __shared__ float smem[];
    u64*   Wd  = (u64*)smem;                    // 176 duplicated params (16B aligned)
    float* Ls  = smem + 176 * 2;                // up to 51*136 logits
    float* red = Ls + 51 * Ww;                  // 16 floats reduction scratch

    const int inst = blockIdx.x >> 1;
    const int half = blockIdx.x & 1;
    const int tid  = threadIdx.x;

    const int r_lo  = half ? 49 : 0;
    const int nrows = half ? 51 : 50;
    const int npix  = nrows * Ww;

    // ---- Phase A: load per-instance params, duplicated for packed math ----
    for (int i = tid; i < NPARAM; i += blockDim.x) {
        float w = params[inst * NPARAM + i];
        Wd[i] = pack2(w, w);
    }
    if (tid == 0) Wd[NPARAM] = 0;  // pad so ull2 load of (168,169) is safe

    const int im  = im_inds[inst];
    const int lvl = fpn_levels[inst];
    const float soi_tab[5] = {8.f, 16.f, 32.f, 64.f, 128.f};
    const float inv_soi = 1.0f / soi_tab[lvl];
    const float lx = locs[inst * 2 + 0];
    const float ly = locs[inst * 2 + 1];
    const float* __restrict__ feat = mask_feats + (size_t)im * 8 * HW + r_lo * Ww;
    __syncthreads();

    const ulonglong2* __restrict__ W2 = (const ulonglong2*)Wd;

    // ---- Phase B: 3-layer MLP, 4 px/thread, LDS.128 weight loads ----
    for (int p0 = tid * 4; p0 < npix; p0 += blockDim.x * 4) {
        int yl = p0 / Ww;
        int x  = p0 - yl * Ww;
        float cy  = (ly - (float)((yl + r_lo) * 8 + 4)) * inv_soi;
        float cx0 = (lx - (float)(x * 8 + 4)) * inv_soi;
        float dx  = -8.f * inv_soi;

        u64 v2[10][2];
        v2[0][0] = pack2(cx0, cx0 + dx);
        v2[0][1] = pack2(cx0 + 2.f * dx, cx0 + 3.f * dx);
        v2[1][0] = pack2(cy, cy);
        v2[1][1] = v2[1][0];
        #pragma unroll
        for (int c = 0; c < 8; c++) {
            float4 f = *reinterpret_cast<const float4*>(feat + c * HW + p0);
            v2[2 + c][0] = pack2(f.x, f.y);
            v2[2 + c][1] = pack2(f.z, f.w);
        }

        u64 h0[8][2];
        #pragma unroll
        for (int c = 0; c < 8; c++) {
            u64 b  = Wd[152 + c];
            u64 a0 = b, a1 = b;
            #pragma unroll
            for (int i2 = 0; i2 < 5; i2++) {           // w0 row: 5 x LDS.128
                ulonglong2 wp = W2[c * 5 + i2];
                a0 = fma2(wp.x, v2[2*i2][0],   a0);
                a1 = fma2(wp.x, v2[2*i2][1],   a1);
                a0 = fma2(wp.y, v2[2*i2+1][0], a0);
                a1 = fma2(wp.y, v2[2*i2+1][1], a1);
            }
            h0[c][0] = relu2(a0);
            h0[c][1] = relu2(a1);
        }

        u64 h1[8][2];
        #pragma unroll
        for (int c = 0; c < 8; c++) {
            u64 b  = Wd[160 + c];
            u64 a0 = b, a1 = b;
            #pragma unroll
            for (int i2 = 0; i2 < 4; i2++) {           // w1 row: 4 x LDS.128
                ulonglong2 wp = W2[40 + c * 4 + i2];
                a0 = fma2(wp.x, h0[2*i2][0],   a0);
                a1 = fma2(wp.x, h0[2*i2][1],   a1);
                a0 = fma2(wp.y, h0[2*i2+1][0], a0);
                a1 = fma2(wp.y, h0[2*i2+1][1], a1);
            }
            h1[c][0] = relu2(a0);
            h1[c][1] = relu2(a1);
        }

        u64 zb = Wd[168];
        u64 z0 = zb, z1 = zb;
        #pragma unroll
        for (int i2 = 0; i2 < 4; i2++) {               // w2: 4 x LDS.128
            ulonglong2 wp = W2[72 + i2];
            z0 = fma2(wp.x, h1[2*i2][0],   z0);
            z1 = fma2(wp.x, h1[2*i2][1],   z1);
            z0 = fma2(wp.y, h1[2*i2+1][0], z0);
            z1 = fma2(wp.y, h1[2*i2+1][1], z1);
        }
        float o0, o1, o2, o3;
        unpack2(z0, o0, o1);
        unpack2(z1, o2, o3);
        *reinterpret_cast<float4*>(Ls + p0) = make_float4(o0, o1, o2, o3);
    }
    __syncthreads();

    // ---- Phase C: aligned_bilinear(x2) + sigmoid + dice partials ----
    float inter = 0.f, ssum = 0.f, tsum = 0.f;
    const float* __restrict__ g = gt + (size_t)inst * OHW + (size_t)(100 * half) * OW;

    for (int q0 = tid * 4; q0 < OHW / 2; q0 += blockDim.x * 4) {
        int yl = q0 / OW;                 // local output row 0..99
        int x0 = q0 - yl * OW;            // multiple of 4
        int k  = x0 >> 2;
        int Y  = yl + 100 * half;         // global output row

        float4 t4 = *reinterpret_cast<const float4*>(g + q0);

        int jy  = max(Y - 1, 0);
        int iy0 = (jy >> 1) - r_lo;       // local logit rows
        int iy1 = iy0 + (jy & 1);
        const float* r0 = Ls + iy0 * Ww;
        const float* r1 = Ls + iy1 * Ww;

        int cm = max(2 * k - 1, 0);
        int c0 = 2 * k;

        float2 a0 = *reinterpret_cast<const float2*>(r0 + c0);
        float2 a1 = *reinterpret_cast<const float2*>(r1 + c0);
        float  m0 = r0[cm];
        float  m1 = r1[cm];

        float em = 0.5f * (m0 + m1);
        float e0 = 0.5f * (a0.x + a1.x);
        float ep = 0.5f * (a0.y + a1.y);

        float z0 = 0.5f * (em + e0);
        float z1 = e0;
        float z2 = 0.5f * (e0 + ep);
        float z3 = ep;

        float s0 = sigm(z0);
        float s1 = sigm(z1);
        float s2 = sigm(z2);
        float s3 = sigm(z3);

        inter = fmaf(s0, t4.x, inter); ssum = fmaf(s0, s0, ssum); tsum = fmaf(t4.x, t4.x, tsum);
        inter = fmaf(s1, t4.y, inter); ssum = fmaf(s1, s1, ssum); tsum = fmaf(t4.y, t4.y, tsum);
        inter = fmaf(s2, t4.z, inter); ssum = fmaf(s2, s2, ssum); tsum = fmaf(t4.z, t4.z, tsum);
        inter = fmaf(s3, t4.w, inter); ssum = fmaf(s3, s3, ssum); tsum = fmaf(t4.w, t4.w, tsum);
    }

    // ---- Phase D: block reduce, accumulate per-instance partials ----
    #pragma unroll
    for (int off = 16; off > 0; off >>= 1) {
        inter += __shfl_down_sync(0xffffffffu, inter, off);
        ssum  += __shfl_down_sync(0xffffffffu, ssum,  off);
        tsum  += __shfl_down_sync(0xffffffffu, tsum,  off);
    }
    int warp = tid >> 5;
    if ((tid & 31) == 0) {
        red[warp]      = inter;
        red[4 + warp]  = ssum;
        red[8 + warp]  = tsum;
    }
    __syncthreads();
    if (tid == 0) {
        float I = red[0] + red[1] + red[2] + red[3];
        float S = red[4] + red[5] + red[6] + red[7];
        float T = red[8] + red[9] + red[10] + red[11];
        atomicAdd(&g_scratch[inst * 3 + 0], I);
        atomicAdd(&g_scratch[inst * 3 + 1], S);
        atomicAdd(&g_scratch[inst * 3 + 2], T);
    }
}

__global__ void dmh_final(float* __restrict__ out, int n_inst, float inv_n) {
    __shared__ float sred[16];
    int tid = threadIdx.x;
    float l = 0.f;
    if (tid < n_inst) {
        float I = g_scratch[tid * 3 + 0];
        float S = g_scratch[tid * 3 + 1];
        float T = g_scratch[tid * 3 + 2];
        l = 1.0f - 2.0f * I / (S + T + 1e-5f);
    }
    #pragma unroll
    for (int off = 16; off > 0; off >>= 1)
        l += __shfl_down_sync(0xffffffffu, l, off);
    if ((tid & 31) == 0) sred[tid >> 5] = l;
    __syncthreads();
    if (tid == 0) {
        float s = 0.f;
        #pragma unroll
        for (int w = 0; w < 16; w++) s += sred[w];
        out[0] = s * inv_n;
    }
}

extern "C" void kernel_launch(void* const* d_in, const int* in_sizes, int n_in,
                              void* d_out, int out_size)
{
    const float* mask_feats = (const float*)d_in[0];
    const float* params     = (const float*)d_in[1];
    const float* locs       = (const float*)d_in[2];
    const float* gt         = (const float*)d_in[3];
    const int*   im_inds    = (const int*)d_in[4];
    const int*   fpn_levels = (const int*)d_in[5];
    float* out = (float*)d_out;

    int n_inst = in_sizes[1] / NPARAM;

    size_t smem_bytes = 176 * sizeof(u64) + 51 * Ww * sizeof(float) + 16 * sizeof(float);
    static int smem_set = 0;
    if (!smem_set) {
        cudaFuncSetAttribute(dmh_kernel, cudaFuncAttributeMaxDynamicSharedMemorySize,
                             (int)smem_bytes);
        smem_set = 1;
    }

    dmh_zero<<<1, 512>>>();
    dmh_kernel<<<2 * n_inst, 128, smem_bytes>>>(mask_feats, params, locs, gt,
                                                im_inds, fpn_levels);
    dmh_final<<<1, 512>>>(out, n_inst, 1.0f / (float)n_inst);
}

// round 6
// speedup vs baseline: 2.3263x; 2.3263x over previous
#include <cuda_runtime.h>
#include <cuda_bf16.h>

#define Hh 100
#define Ww 136
#define HW (Hh*Ww)      // 13600
#define OH 200
#define OW 272
#define OHW (OH*OW)     // 54400
#define NPARAM 169

typedef unsigned long long u64;

// ---- packed f32x2 helpers ----
__device__ __forceinline__ u64 pack2(float a, float b) {
    u64 r; asm("mov.b64 %0, {%1, %2};" : "=l"(r) : "f"(a), "f"(b)); return r;
}
__device__ __forceinline__ void unpack2(u64 v, float& a, float& b) {
    asm("mov.b64 {%0, %1}, %2;" : "=f"(a), "=f"(b) : "l"(v));
}
__device__ __forceinline__ u64 fma2(u64 a, u64 b, u64 c) {
    u64 d; asm("fma.rn.f32x2 %0, %1, %2, %3;" : "=l"(d) : "l"(a), "l"(b), "l"(c)); return d;
}
__device__ __forceinline__ u64 relu2(u64 v) {
    float a, b; unpack2(v, a, b);
    return pack2(fmaxf(a, 0.f), fmaxf(b, 0.f));
}
__device__ __forceinline__ float sigm(float z) {
    float t; asm("tanh.approx.f32 %0, %1;" : "=f"(t) : "f"(z * 0.5f));
    return fmaf(t, 0.5f, 0.5f);
}

// params layout: w0[8][10]@0, w1[8][8]@80, w2[8]@144, b0[8]@152, b1[8]@160, b2@168

__global__ void dmh_zero(float* out) { out[0] = 0.0f; }

__global__ void __launch_bounds__(256)
dmh_kernel(const float* __restrict__ mask_feats,
           const float* __restrict__ params,
           const float* __restrict__ locs,
           const float* __restrict__ gt,
           const int*   __restrict__ im_inds,
           const int*   __restrict__ fpn_levels,
           float* __restrict__ out,
           float inv_n)
{
    extern __shared__ float smem[];
    float* Ls  = smem;                          // HW logits
    u64*   Wd  = (u64*)(smem + HW);             // 169 duplicated params {w,w}
    float* red = (float*)(Wd + NPARAM + 1);     // 24 floats reduction scratch

    const int inst = blockIdx.x;
    const int tid  = threadIdx.x;

    // ---- Phase A: load per-instance params, duplicated for packed math ----
    for (int i = tid; i < NPARAM; i += blockDim.x) {
        float w = params[inst * NPARAM + i];
        Wd[i] = pack2(w, w);
    }

    const int im  = im_inds[inst];
    const int lvl = fpn_levels[inst];
    const float soi_tab[5] = {8.f, 16.f, 32.f, 64.f, 128.f};
    const float inv_soi = 1.0f / soi_tab[lvl];
    const float lx = locs[inst * 2 + 0];
    const float ly = locs[inst * 2 + 1];
    const float* __restrict__ feat = mask_feats + (size_t)im * 8 * HW;
    __syncthreads();

    // ---- Phase B: per-pixel 3-layer MLP with packed f32x2 FMA (4 px/thread) ----
    for (int p0 = tid * 4; p0 < HW; p0 += blockDim.x * 4) {
        int y = p0 / Ww;
        int x = p0 - y * Ww;
        float cy  = (ly - (float)(y * 8 + 4)) * inv_soi;
        float cx0 = (lx - (float)(x * 8 + 4)) * inv_soi;
        float dx  = -8.f * inv_soi;

        u64 v2[10][2];
        v2[0][0] = pack2(cx0, cx0 + dx);
        v2[0][1] = pack2(cx0 + 2.f * dx, cx0 + 3.f * dx);
        v2[1][0] = pack2(cy, cy);
        v2[1][1] = v2[1][0];
        #pragma unroll
        for (int c = 0; c < 8; c++) {
            float4 f = *reinterpret_cast<const float4*>(feat + c * HW + p0);
            v2[2 + c][0] = pack2(f.x, f.y);
            v2[2 + c][1] = pack2(f.z, f.w);
        }

        u64 h0[8][2];
        #pragma unroll
        for (int c = 0; c < 8; c++) {
            u64 b  = Wd[152 + c];
            u64 a0 = b, a1 = b;
            #pragma unroll
            for (int i = 0; i < 10; i++) {
                u64 w = Wd[c * 10 + i];
                a0 = fma2(w, v2[i][0], a0);
                a1 = fma2(w, v2[i][1], a1);
            }
            h0[c][0] = relu2(a0);
            h0[c][1] = relu2(a1);
        }

        u64 h1[8][2];
        #pragma unroll
        for (int c = 0; c < 8; c++) {
            u64 b  = Wd[160 + c];
            u64 a0 = b, a1 = b;
            #pragma unroll
            for (int i = 0; i < 8; i++) {
                u64 w = Wd[80 + c * 8 + i];
                a0 = fma2(w, h0[i][0], a0);
                a1 = fma2(w, h0[i][1], a1);
            }
            h1[c][0] = relu2(a0);
            h1[c][1] = relu2(a1);
        }

        u64 zb = Wd[168];
        u64 z0 = zb, z1 = zb;
        #pragma unroll
        for (int i = 0; i < 8; i++) {
            u64 w = Wd[144 + i];
            z0 = fma2(w, h1[i][0], z0);
            z1 = fma2(w, h1[i][1], z1);
        }
        float o0, o1, o2, o3;
        unpack2(z0, o0, o1);
        unpack2(z1, o2, o3);
        *reinterpret_cast<float4*>(Ls + p0) = make_float4(o0, o1, o2, o3);
    }
    __syncthreads();

    // ---- Phase C: 16 px/thread, 4 batched LDG.128 (MLP=4) ----
    // OW = 272 = 17 * 16 -> 16-px chunks never cross a row.
    float inter = 0.f, ssum = 0.f, tsum = 0.f;
    const float* __restrict__ g = gt + (size_t)inst * OHW;
    const int NCHUNK = OHW / 16;   // 3400

    for (int ch = tid; ch < NCHUNK; ch += blockDim.x) {
        int y  = ch / 17;
        int xc = (ch - y * 17) * 16;        // output x of chunk start
        int q0 = y * OW + xc;

        // 4 independent global loads, issued back-to-back
        float4 t0 = *reinterpret_cast<const float4*>(g + q0);
        float4 t1 = *reinterpret_cast<const float4*>(g + q0 + 4);
        float4 t2 = *reinterpret_cast<const float4*>(g + q0 + 8);
        float4 t3 = *reinterpret_cast<const float4*>(g + q0 + 12);

        int jy  = max(y - 1, 0);
        int iy0 = jy >> 1;
        int iy1 = iy0 + (jy & 1);
        const float* r0 = Ls + iy0 * Ww;
        const float* r1 = Ls + iy1 * Ww;

        int c0 = xc >> 1;                   // = 2*k0, multiple of 8 -> 16B aligned
        int cm = max(c0 - 1, 0);

        float4 A0 = *reinterpret_cast<const float4*>(r0 + c0);
        float4 B0 = *reinterpret_cast<const float4*>(r0 + c0 + 4);
        float4 A1 = *reinterpret_cast<const float4*>(r1 + c0);
        float4 B1 = *reinterpret_cast<const float4*>(r1 + c0 + 4);
        float  m0 = r0[cm];
        float  m1 = r1[cm];

        // vertical blend (rows equal on even output rows -> exact passthrough)
        float Em = 0.5f * (m0 + m1);
        float E[8];
        E[0] = 0.5f * (A0.x + A1.x);
        E[1] = 0.5f * (A0.y + A1.y);
        E[2] = 0.5f * (A0.z + A1.z);
        E[3] = 0.5f * (A0.w + A1.w);
        E[4] = 0.5f * (B0.x + B1.x);
        E[5] = 0.5f * (B0.y + B1.y);
        E[6] = 0.5f * (B0.z + B1.z);
        E[7] = 0.5f * (B0.w + B1.w);

        // horizontal: x=4j -> 0.5(E[2j-1]+E[2j]) (Em for j=0; clamp makes x=0 exact),
        //             4j+1 -> E[2j], 4j+2 -> 0.5(E[2j]+E[2j+1]), 4j+3 -> E[2j+1]
        float gtv[16] = {t0.x, t0.y, t0.z, t0.w, t1.x, t1.y, t1.z, t1.w,
                         t2.x, t2.y, t2.z, t2.w, t3.x, t3.y, t3.z, t3.w};
        #pragma unroll
        for (int j = 0; j < 4; j++) {
            float ep = (j == 0) ? Em : E[2 * j - 1];
            float e0 = E[2 * j];
            float e1 = E[2 * j + 1];
            float s0 = sigm(0.5f * (ep + e0));
            float s1 = sigm(e0);
            float s2 = sigm(0.5f * (e0 + e1));
            float s3 = sigm(e1);
            float g0 = gtv[4 * j + 0], g1 = gtv[4 * j + 1];
            float g2 = gtv[4 * j + 2], g3 = gtv[4 * j + 3];
            inter = fmaf(s0, g0, inter); ssum = fmaf(s0, s0, ssum); tsum = fmaf(g0, g0, tsum);
            inter = fmaf(s1, g1, inter); ssum = fmaf(s1, s1, ssum); tsum = fmaf(g1, g1, tsum);
            inter = fmaf(s2, g2, inter); ssum = fmaf(s2, s2, ssum); tsum = fmaf(g2, g2, tsum);
            inter = fmaf(s3, g3, inter); ssum = fmaf(s3, s3, ssum); tsum = fmaf(g3, g3, tsum);
        }
    }

    // ---- Phase D: block reduce, per-instance dice, atomic mean ----
    #pragma unroll
    for (int off = 16; off > 0; off >>= 1) {
        inter += __shfl_down_sync(0xffffffffu, inter, off);
        ssum  += __shfl_down_sync(0xffffffffu, ssum,  off);
        tsum  += __shfl_down_sync(0xffffffffu, tsum,  off);
    }
    int warp = tid >> 5;
    if ((tid & 31) == 0) {
        red[warp]      = inter;
        red[8 + warp]  = ssum;
        red[16 + warp] = tsum;
    }
    __syncthreads();
    if (tid == 0) {
        float I = 0.f, S = 0.f, T = 0.f;
        #pragma unroll
        for (int w = 0; w < 8; w++) { I += red[w]; S += red[8 + w]; T += red[16 + w]; }
        float loss = 1.0f - 2.0f * I / (S + T + 1e-5f);
        atomicAdd(out, loss * inv_n);
    }
}

extern "C" void kernel_launch(void* const* d_in, const int* in_sizes, int n_in,
                              void* d_out, int out_size)
{
    const float* mask_feats = (const float*)d_in[0];
    const float* params     = (const float*)d_in[1];
    const float* locs       = (const float*)d_in[2];
    const float* gt         = (const float*)d_in[3];
    const int*   im_inds    = (const int*)d_in[4];
    const int*   fpn_levels = (const int*)d_in[5];
    float* out = (float*)d_out;

    int n_inst = in_sizes[1] / NPARAM;

    static int smem_set = 0;
    size_t smem_bytes = HW * sizeof(float) + (NPARAM + 1) * sizeof(u64) + 32 * sizeof(float);
    if (!smem_set) {
        cudaFuncSetAttribute(dmh_kernel, cudaFuncAttributeMaxDynamicSharedMemorySize,
                             (int)smem_bytes);
        smem_set = 1;
    }

    dmh_zero<<<1, 1>>>(out);
    dmh_kernel<<<n_inst, 256, smem_bytes>>>(mask_feats, params, locs, gt,
                                            im_inds, fpn_levels, out,
                                            1.0f / (float)n_inst);
}